// round 1
// baseline (speedup 1.0000x reference)
#include <cuda_runtime.h>

#define B_ 8
#define N_ 1024
#define E_ 1024
#define H_ 16
#define D_ 64
#define RES_ 32

// Scratch (static device globals: allocation-free per harness rules)
__device__ float g_q[B_ * H_ * N_ * D_];
__device__ float g_k[B_ * H_ * N_ * D_];
__device__ float g_v[B_ * H_ * N_ * D_];
__device__ float g_ao[B_ * N_ * E_];

// ---------------------------------------------------------------------------
// SGEMM (NT): C[m,n] = sum_k A[m,k] * B[n,k]
// BM=BN=128, BK=8, 256 threads, 8x8 per-thread microtile.
// MODE 0: qkv projection epilogue (scatter to g_q/g_k/g_v, q pre-scaled)
// MODE 1: output projection epilogue (C = acc + bias[n] -> Cout)
// ---------------------------------------------------------------------------
template <int MODE>
__global__ __launch_bounds__(256) void sgemm_nt(
    const float* __restrict__ A, const float* __restrict__ Bm,
    const float* __restrict__ bias, float* __restrict__ Cout,
    int M, int Nn, int K)
{
    __shared__ float As[8][132];
    __shared__ float Bs[8][132];

    const int tid = threadIdx.x;
    const int bm = blockIdx.y * 128;
    const int bn = blockIdx.x * 128;
    const int lrow = tid >> 1;          // 0..127
    const int lcol = (tid & 1) * 4;     // 0 or 4
    const int tx = tid & 15;
    const int ty = tid >> 4;

    const float* Aptr = A + (size_t)(bm + lrow) * K + lcol;
    const float* Bptr = Bm + (size_t)(bn + lrow) * K + lcol;

    float acc[8][8];
#pragma unroll
    for (int i = 0; i < 8; i++)
#pragma unroll
        for (int j = 0; j < 8; j++) acc[i][j] = 0.f;

    for (int k0 = 0; k0 < K; k0 += 8) {
        float4 av = *(const float4*)(Aptr + k0);
        float4 bv = *(const float4*)(Bptr + k0);
        __syncthreads();
        As[lcol + 0][lrow] = av.x; As[lcol + 1][lrow] = av.y;
        As[lcol + 2][lrow] = av.z; As[lcol + 3][lrow] = av.w;
        Bs[lcol + 0][lrow] = bv.x; Bs[lcol + 1][lrow] = bv.y;
        Bs[lcol + 2][lrow] = bv.z; Bs[lcol + 3][lrow] = bv.w;
        __syncthreads();
#pragma unroll
        for (int k = 0; k < 8; k++) {
            float af[8], bf[8];
            *(float4*)&af[0] = *(const float4*)&As[k][ty * 8];
            *(float4*)&af[4] = *(const float4*)&As[k][ty * 8 + 4];
            *(float4*)&bf[0] = *(const float4*)&Bs[k][tx * 8];
            *(float4*)&bf[4] = *(const float4*)&Bs[k][tx * 8 + 4];
#pragma unroll
            for (int i = 0; i < 8; i++)
#pragma unroll
                for (int j = 0; j < 8; j++)
                    acc[i][j] += af[i] * bf[j];
        }
    }

    if (MODE == 0) {
        // n in [0,3072): which = n/1024 (q/k/v), e = n%1024, h = e/64, d = e%64
        const int which = bn >> 10;
        float* base = (which == 0) ? g_q : ((which == 1) ? g_k : g_v);
        const float sc = (which == 0) ? 0.125f : 1.0f;  // D^-0.5 = 1/8
        const int e0 = (bn & 1023) + tx * 8;
        const int h = e0 >> 6;
        const int d = e0 & 63;   // multiple of 8, within a single head
#pragma unroll
        for (int i = 0; i < 8; i++) {
            int m = bm + ty * 8 + i;
            int b = m >> 10, t = m & 1023;
            float* dst = base + ((size_t)((b << 4) + h) * N_ + t) * D_ + d;
            float4 v0 = make_float4(acc[i][0] * sc, acc[i][1] * sc,
                                    acc[i][2] * sc, acc[i][3] * sc);
            float4 v1 = make_float4(acc[i][4] * sc, acc[i][5] * sc,
                                    acc[i][6] * sc, acc[i][7] * sc);
            *(float4*)dst = v0;
            *(float4*)(dst + 4) = v1;
        }
    } else {
        const int n0 = bn + tx * 8;
        float bb[8];
#pragma unroll
        for (int j = 0; j < 8; j++) bb[j] = bias[n0 + j];
#pragma unroll
        for (int i = 0; i < 8; i++) {
            int m = bm + ty * 8 + i;
            float* dst = Cout + (size_t)m * Nn + n0;
            float4 v0 = make_float4(acc[i][0] + bb[0], acc[i][1] + bb[1],
                                    acc[i][2] + bb[2], acc[i][3] + bb[3]);
            float4 v1 = make_float4(acc[i][4] + bb[4], acc[i][5] + bb[5],
                                    acc[i][6] + bb[6], acc[i][7] + bb[7]);
            *(float4*)dst = v0;
            *(float4*)(dst + 4) = v1;
        }
    }
}

// ---------------------------------------------------------------------------
// Fused attention: one CTA per (b*H + h, 64-row query tile).
// Online softmax over 16 K/V tiles of 64. Relative-position bias computed
// from token coordinates on the fly (bias_idxs input unused).
// Thread map: 16x16, thread (ty,tx) owns rows {ty+16i} and cols {tx+16j}.
// ---------------------------------------------------------------------------
#define ATTN_SMEM_FLOATS (64 * 64 + 64 * 65 + 64 * 64 + 64 * 65 + 1024)
#define ATTN_SMEM_BYTES (ATTN_SMEM_FLOATS * 4)

__global__ __launch_bounds__(256) void attn_kernel(
    const float* __restrict__ gq, const float* __restrict__ gk,
    const float* __restrict__ gv, const float* __restrict__ biases,
    float* __restrict__ gao)
{
    extern __shared__ float sm[];
    float* Qs = sm;                     // [64][64]
    float* Ks = Qs + 64 * 64;           // [64][65]  (pitch 65 -> conflict-free col reads)
    float* Vs = Ks + 64 * 65;           // [64][64]
    float* Ps = Vs + 64 * 64;           // [64][65]
    float* bias_s = Ps + 64 * 65;       // [1024]

    const int tid = threadIdx.x;
    const int tx = tid & 15, ty = tid >> 4;
    const int bh = blockIdx.y;
    const int b = bh >> 4, h = bh & 15;
    const int q0 = blockIdx.x * 64;

    const float* Qg = gq + ((size_t)bh * N_ + q0) * D_;
    const float* Kg = gk + (size_t)bh * N_ * D_;
    const float* Vg = gv + (size_t)bh * N_ * D_;

    // Load Q tile (float4, pitch 64 keeps alignment) and bias table
    for (int idx = tid; idx < 64 * 16; idx += 256) {
        int r = idx >> 4;
        int d4 = (idx & 15) * 4;
        *(float4*)&Qs[r * 64 + d4] = *(const float4*)&Qg[r * 64 + d4];
    }
    for (int idx = tid; idx < 1024; idx += 256)
        bias_s[idx] = biases[h * 1024 + idx];

    float m_i[4], l_i[4], O[4][4];
#pragma unroll
    for (int i = 0; i < 4; i++) {
        m_i[i] = -1e30f;
        l_i[i] = 0.f;
#pragma unroll
        for (int j = 0; j < 4; j++) O[i][j] = 0.f;
    }

    int rri[4], cci[4];
#pragma unroll
    for (int i = 0; i < 4; i++) {
        int ig = q0 + ty + 16 * i;
        rri[i] = ig >> 5;
        cci[i] = ig & 31;
    }

    for (int kt = 0; kt < 16; kt++) {
        const int k0t = kt * 64;
        __syncthreads();  // previous-iteration Ks/Vs/Ps reads complete

        // Load K (pitch 65: scalar stores) and V (pitch 64: float4) tiles
        for (int idx = tid; idx < 64 * 16; idx += 256) {
            int r = idx >> 4;
            int d4 = (idx & 15) * 4;
            float4 kv = *(const float4*)&Kg[(size_t)(k0t + r) * 64 + d4];
            Ks[r * 65 + d4 + 0] = kv.x;
            Ks[r * 65 + d4 + 1] = kv.y;
            Ks[r * 65 + d4 + 2] = kv.z;
            Ks[r * 65 + d4 + 3] = kv.w;
            *(float4*)&Vs[r * 64 + d4] = *(const float4*)&Vg[(size_t)(k0t + r) * 64 + d4];
        }
        __syncthreads();

        // S = Q K^T  (q already pre-scaled by 1/8)
        float s[4][4];
#pragma unroll
        for (int i = 0; i < 4; i++)
#pragma unroll
            for (int j = 0; j < 4; j++) s[i][j] = 0.f;

#pragma unroll 16
        for (int d = 0; d < 64; d++) {
            float qv[4], kv[4];
#pragma unroll
            for (int i = 0; i < 4; i++) qv[i] = Qs[(ty + 16 * i) * 64 + d];
#pragma unroll
            for (int j = 0; j < 4; j++) kv[j] = Ks[(tx + 16 * j) * 65 + d];
#pragma unroll
            for (int i = 0; i < 4; i++)
#pragma unroll
                for (int j = 0; j < 4; j++)
                    s[i][j] += qv[i] * kv[j];
        }

        // Relative-position bias (computed, not gathered from int table)
#pragma unroll
        for (int j = 0; j < 4; j++) {
            int jg = k0t + tx + 16 * j;
            int rj = jg >> 5, cj = jg & 31;
#pragma unroll
            for (int i = 0; i < 4; i++) {
                int dr = abs(rri[i] - rj);
                int dc = abs(cci[i] - cj);
                s[i][j] += bias_s[dr * 32 + dc];
            }
        }

        // Online softmax (row stats reduced over the 16 tx lanes)
#pragma unroll
        for (int i = 0; i < 4; i++) {
            float mloc = fmaxf(fmaxf(s[i][0], s[i][1]), fmaxf(s[i][2], s[i][3]));
#pragma unroll
            for (int off = 8; off >= 1; off >>= 1)
                mloc = fmaxf(mloc, __shfl_xor_sync(0xffffffffu, mloc, off));
            float mnew = fmaxf(m_i[i], mloc);
            float alpha = __expf(m_i[i] - mnew);
            m_i[i] = mnew;
            float rsum = 0.f;
#pragma unroll
            for (int j = 0; j < 4; j++) {
                s[i][j] = __expf(s[i][j] - mnew);
                rsum += s[i][j];
            }
#pragma unroll
            for (int off = 8; off >= 1; off >>= 1)
                rsum += __shfl_xor_sync(0xffffffffu, rsum, off);
            l_i[i] = l_i[i] * alpha + rsum;
#pragma unroll
            for (int j = 0; j < 4; j++) O[i][j] *= alpha;
        }

        // Publish P tile
#pragma unroll
        for (int i = 0; i < 4; i++)
#pragma unroll
            for (int j = 0; j < 4; j++)
                Ps[(ty + 16 * i) * 65 + tx + 16 * j] = s[i][j];
        __syncthreads();

        // O += P @ V
#pragma unroll 16
        for (int jj = 0; jj < 64; jj++) {
            float pv[4], vv[4];
#pragma unroll
            for (int i = 0; i < 4; i++) pv[i] = Ps[(ty + 16 * i) * 65 + jj];
#pragma unroll
            for (int j = 0; j < 4; j++) vv[j] = Vs[jj * 64 + tx + 16 * j];
#pragma unroll
            for (int i = 0; i < 4; i++)
#pragma unroll
                for (int j = 0; j < 4; j++)
                    O[i][j] += pv[i] * vv[j];
        }
    }

    // Epilogue: normalize and write token-major [b, t, h*64 + d]
#pragma unroll
    for (int i = 0; i < 4; i++) {
        float inv = 1.f / l_i[i];
        int t = q0 + ty + 16 * i;
        float* dst = gao + ((size_t)(b * N_ + t)) * E_ + h * 64;
#pragma unroll
        for (int j = 0; j < 4; j++)
            dst[tx + 16 * j] = O[i][j] * inv;
    }
}

// ---------------------------------------------------------------------------
extern "C" void kernel_launch(void* const* d_in, const int* in_sizes, int n_in,
                              void* d_out, int out_size)
{
    (void)in_sizes; (void)n_in; (void)out_size;
    const float* x      = (const float*)d_in[0];  // [8, 1024, 1024]
    const float* w_qkv  = (const float*)d_in[1];  // [3072, 1024]
    const float* biases = (const float*)d_in[2];  // [16, 1024]
    // d_in[3] = bias_idxs: unused (recomputed analytically in-kernel)
    const float* w_out  = (const float*)d_in[4];  // [1024, 1024]
    const float* b_out  = (const float*)d_in[5];  // [1024]
    float* out = (float*)d_out;                   // [8, 1024, 1024]

    float* gq; cudaGetSymbolAddress((void**)&gq, g_q);
    float* gk; cudaGetSymbolAddress((void**)&gk, g_k);
    float* gv; cudaGetSymbolAddress((void**)&gv, g_v);
    float* gao; cudaGetSymbolAddress((void**)&gao, g_ao);

    // 1) QKV projection: [8192,1024] x [3072,1024]^T -> scatter q/k/v head-major
    {
        dim3 grid(3072 / 128, 8192 / 128);
        sgemm_nt<0><<<grid, 256>>>(x, w_qkv, nullptr, nullptr, 8192, 3072, 1024);
    }

    // 2) Fused attention with relative-position bias
    {
        cudaFuncSetAttribute(attn_kernel,
                             cudaFuncAttributeMaxDynamicSharedMemorySize,
                             ATTN_SMEM_BYTES);
        dim3 grid(N_ / 64, B_ * H_);
        attn_kernel<<<grid, 256, ATTN_SMEM_BYTES>>>(gq, gk, gv, biases, gao);
    }

    // 3) Output projection: [8192,1024] x [1024,1024]^T + b_out
    {
        dim3 grid(1024 / 128, 8192 / 128);
        sgemm_nt<1><<<grid, 256>>>(gao, w_out, b_out, out, 8192, 1024, 1024);
    }
}

// round 3
// speedup vs baseline: 1.6466x; 1.6466x over previous
#include <cuda_runtime.h>
#include <cuda_bf16.h>
#include <cstdint>

#define B_ 8
#define N_ 1024
#define E_ 1024
#define H_ 16
#define D_ 64

// ---------------------------------------------------------------------------
// Static scratch (allocation-free)
// ---------------------------------------------------------------------------
__device__ __align__(16) float         g_qkv[(size_t)8192 * 3072];   // fused q|k|v fp32
__device__ __align__(16) float         g_ao [(size_t)8192 * 1024];
__device__ __align__(16) __nv_bfloat16 g_ahi[(size_t)8192 * 1024];
__device__ __align__(16) __nv_bfloat16 g_alo[(size_t)8192 * 1024];
__device__ __align__(16) __nv_bfloat16 g_w1hi[(size_t)3072 * 1024];
__device__ __align__(16) __nv_bfloat16 g_w1lo[(size_t)3072 * 1024];
__device__ __align__(16) __nv_bfloat16 g_w2hi[(size_t)1024 * 1024];
__device__ __align__(16) __nv_bfloat16 g_w2lo[(size_t)1024 * 1024];
__device__ __align__(16) __nv_bfloat16 g_aohi[(size_t)8192 * 1024];
__device__ __align__(16) __nv_bfloat16 g_aolo[(size_t)8192 * 1024];

__device__ __forceinline__ uint32_t smem_to_u32(const void* p) {
    uint32_t a;
    asm("{ .reg .u64 t; cvta.to.shared.u64 t, %1; cvt.u32.u64 %0, t; }" : "=r"(a) : "l"(p));
    return a;
}
#define SWZ(o) ((o) ^ (((o) >> 3) & 0x70))

__device__ __forceinline__ void ldsm_x4(uint32_t* d, uint32_t addr) {
    asm volatile("ldmatrix.sync.aligned.m8n8.x4.shared.b16 {%0,%1,%2,%3}, [%4];"
                 : "=r"(d[0]), "=r"(d[1]), "=r"(d[2]), "=r"(d[3]) : "r"(addr));
}
__device__ __forceinline__ void mma_bf16(float* c, const uint32_t* a, uint32_t b0, uint32_t b1) {
    asm volatile(
        "mma.sync.aligned.m16n8k16.row.col.f32.bf16.bf16.f32 "
        "{%0,%1,%2,%3}, {%4,%5,%6,%7}, {%8,%9}, {%0,%1,%2,%3};"
        : "+f"(c[0]), "+f"(c[1]), "+f"(c[2]), "+f"(c[3])
        : "r"(a[0]), "r"(a[1]), "r"(a[2]), "r"(a[3]), "r"(b0), "r"(b1));
}
__device__ __forceinline__ void cp_async16(uint32_t sdst, const void* gsrc) {
    asm volatile("cp.async.cg.shared.global [%0], [%1], 16;" :: "r"(sdst), "l"(gsrc));
}
#define CP_COMMIT() asm volatile("cp.async.commit_group;" ::: "memory")
#define CP_WAIT_ALL() asm volatile("cp.async.wait_group 0;" ::: "memory")

// ---------------------------------------------------------------------------
// fp32 -> (bf16 hi, bf16 lo) split
// ---------------------------------------------------------------------------
__global__ __launch_bounds__(256) void split_bf16(
    const float* __restrict__ x, __nv_bfloat16* __restrict__ hi,
    __nv_bfloat16* __restrict__ lo, int n4)
{
    int i = blockIdx.x * 256 + threadIdx.x;
    if (i >= n4) return;
    float4 v = ((const float4*)x)[i];
    float vv[4] = {v.x, v.y, v.z, v.w};
    ushort4 h, l;
    unsigned short* hp = &h.x;
    unsigned short* lp = &l.x;
#pragma unroll
    for (int j = 0; j < 4; j++) {
        __nv_bfloat16 bh = __float2bfloat16_rn(vv[j]);
        __nv_bfloat16 bl = __float2bfloat16_rn(vv[j] - __bfloat162float(bh));
        hp[j] = *reinterpret_cast<unsigned short*>(&bh);
        lp[j] = *reinterpret_cast<unsigned short*>(&bl);
    }
    ((ushort4*)hi)[i] = h;
    ((ushort4*)lo)[i] = l;
}

// ---------------------------------------------------------------------------
// HMMA bf16-split GEMM (NT): C[m,n] = sum_k A[m,k]*B[n,k], K=1024, fp32 out.
// 128x128 CTA tile, 8 warps (4m x 2n), BK=64, cp.async double buffer.
// 3 terms: Ah*Bh + Ah*Bl + Al*Bh.
// MODE 0: C = g_qkv (ldc 3072), q block (bn<1024) scaled by 0.125
// MODE 1: C = out + bias[n] (ldc 1024)
// ---------------------------------------------------------------------------
#define STAGE_BYTES 65536
#define GEMM_SMEM (2 * STAGE_BYTES)

template <int MODE>
__global__ __launch_bounds__(256, 1)
void gemm_hmma(const __nv_bfloat16* __restrict__ Ah, const __nv_bfloat16* __restrict__ Al,
               const __nv_bfloat16* __restrict__ Bh, const __nv_bfloat16* __restrict__ Bl,
               const float* __restrict__ bias, float* __restrict__ C, int ldc)
{
    extern __shared__ char smem[];
    const uint32_t sb = smem_to_u32(smem);
    const int tid = threadIdx.x;
    const int wid = tid >> 5, lane = tid & 31;
    const int bm = blockIdx.y * 128, bn = blockIdx.x * 128;
    const int wm = wid >> 1, wn = wid & 1;

    // global tile base pointers (row stride 1024 bf16)
    const __nv_bfloat16* tb[4] = {
        Ah + (size_t)bm * 1024, Al + (size_t)bm * 1024,
        Bh + (size_t)bn * 1024, Bl + (size_t)bn * 1024 };

    // load mapping: thread -> (row block, 16B chunk)
    const int rb = tid >> 3;        // 0..31
    const int cg = tid & 7;         // 0..7
    uint32_t soff[4];
#pragma unroll
    for (int it = 0; it < 4; it++)
        soff[it] = SWZ((uint32_t)((rb + it * 32) * 128 + cg * 16));

    // ldmatrix per-lane geometry
    const int q = lane >> 3, l8 = lane & 7;
    const int ar = wm * 32 + (q & 1) * 8 + l8;   // + mt*16
    const int ac = (q >> 1) * 16;                // + ks*32 (bytes)
    const int br = wn * 64 + (q >> 1) * 8 + l8;  // + jp*16
    const int bc = (q & 1) * 16;                 // + ks*32 (bytes)

    float acc[2][8][4];
#pragma unroll
    for (int mt = 0; mt < 2; mt++)
#pragma unroll
        for (int nt = 0; nt < 8; nt++)
#pragma unroll
            for (int e = 0; e < 4; e++) acc[mt][nt][e] = 0.f;

#define ISSUE(kc_, buf_) do {                                                   \
    const uint32_t stage = sb + (uint32_t)(buf_) * STAGE_BYTES;                 \
    _Pragma("unroll")                                                           \
    for (int t = 0; t < 4; t++) {                                               \
        const __nv_bfloat16* gp = tb[t] + (size_t)(kc_) * 64 + cg * 8;          \
        const uint32_t tbase = stage + (uint32_t)t * 16384u;                    \
        _Pragma("unroll")                                                       \
        for (int it = 0; it < 4; it++)                                          \
            cp_async16(tbase + soff[it], gp + (size_t)(rb + it * 32) * 1024);   \
    }                                                                           \
    CP_COMMIT();                                                                \
} while (0)

    ISSUE(0, 0);

    for (int kc = 0; kc < 16; kc++) {
        const int buf = kc & 1;
        CP_WAIT_ALL();
        __syncthreads();
        if (kc < 15) ISSUE(kc + 1, buf ^ 1);

        const uint32_t stage = sb + (uint32_t)buf * STAGE_BYTES;
        const uint32_t sAh = stage, sAl = stage + 16384u;
        const uint32_t sBh = stage + 32768u, sBl = stage + 49152u;

#pragma unroll
        for (int ks = 0; ks < 4; ks++) {
            uint32_t ah[2][4], al[2][4];
#pragma unroll
            for (int mt = 0; mt < 2; mt++) {
                const uint32_t off = SWZ((uint32_t)((ar + mt * 16) * 128 + ac + ks * 32));
                ldsm_x4(ah[mt], sAh + off);
                ldsm_x4(al[mt], sAl + off);
            }
            uint32_t bh[4][4], bl[4][4];
#pragma unroll
            for (int jp = 0; jp < 4; jp++) {
                const uint32_t off = SWZ((uint32_t)((br + jp * 16) * 128 + bc + ks * 32));
                ldsm_x4(bh[jp], sBh + off);
                ldsm_x4(bl[jp], sBl + off);
            }
#pragma unroll
            for (int mt = 0; mt < 2; mt++)
#pragma unroll
                for (int jp = 0; jp < 4; jp++) {
                    mma_bf16(acc[mt][2 * jp + 0], ah[mt], bh[jp][0], bh[jp][1]);
                    mma_bf16(acc[mt][2 * jp + 1], ah[mt], bh[jp][2], bh[jp][3]);
                    mma_bf16(acc[mt][2 * jp + 0], ah[mt], bl[jp][0], bl[jp][1]);
                    mma_bf16(acc[mt][2 * jp + 1], ah[mt], bl[jp][2], bl[jp][3]);
                    mma_bf16(acc[mt][2 * jp + 0], al[mt], bh[jp][0], bh[jp][1]);
                    mma_bf16(acc[mt][2 * jp + 1], al[mt], bh[jp][2], bh[jp][3]);
                }
        }
        __syncthreads();
    }
#undef ISSUE

    // Epilogue
    const int g = lane >> 2, tg = lane & 3;
#pragma unroll
    for (int mt = 0; mt < 2; mt++) {
        const int row0 = bm + wm * 32 + mt * 16 + g;
#pragma unroll
        for (int nt = 0; nt < 8; nt++) {
            const int col = bn + wn * 64 + nt * 8 + tg * 2;
            float v0 = acc[mt][nt][0], v1 = acc[mt][nt][1];
            float v2 = acc[mt][nt][2], v3 = acc[mt][nt][3];
            if (MODE == 0) {
                const float sc = (bn < 1024) ? 0.125f : 1.0f;
                v0 *= sc; v1 *= sc; v2 *= sc; v3 *= sc;
            } else {
                const float b0v = bias[col], b1v = bias[col + 1];
                v0 += b0v; v1 += b1v; v2 += b0v; v3 += b1v;
            }
            *(float2*)(C + (size_t)row0 * ldc + col)       = make_float2(v0, v1);
            *(float2*)(C + (size_t)(row0 + 8) * ldc + col) = make_float2(v2, v3);
        }
    }
}

// ---------------------------------------------------------------------------
// Fused attention (fp32) reading fused qkv [8192, 3072]
// ---------------------------------------------------------------------------
#define ATTN_SMEM_FLOATS (64 * 64 + 64 * 65 + 64 * 64 + 64 * 65 + 1024)
#define ATTN_SMEM_BYTES (ATTN_SMEM_FLOATS * 4)

__global__ __launch_bounds__(256) void attn_kernel(
    const float* __restrict__ qkv, const float* __restrict__ biases,
    float* __restrict__ gao)
{
    extern __shared__ float sm[];
    float* Qs = sm;
    float* Ks = Qs + 64 * 64;
    float* Vs = Ks + 64 * 65;
    float* Ps = Vs + 64 * 64;
    float* bias_s = Ps + 64 * 65;

    const int tid = threadIdx.x;
    const int tx = tid & 15, ty = tid >> 4;
    const int bh = blockIdx.y;
    const int b = bh >> 4, h = bh & 15;
    const int q0 = blockIdx.x * 64;

    const float* Qg = qkv + ((size_t)(b * N_) + q0) * 3072 + h * 64;
    const float* Kg = qkv + (size_t)(b * N_) * 3072 + 1024 + h * 64;
    const float* Vg = Kg + 1024;

    for (int idx = tid; idx < 64 * 16; idx += 256) {
        int r = idx >> 4;
        int d4 = (idx & 15) * 4;
        *(float4*)&Qs[r * 64 + d4] = *(const float4*)&Qg[(size_t)r * 3072 + d4];
    }
    for (int idx = tid; idx < 1024; idx += 256)
        bias_s[idx] = biases[h * 1024 + idx];

    float m_i[4], l_i[4], O[4][4];
#pragma unroll
    for (int i = 0; i < 4; i++) {
        m_i[i] = -1e30f; l_i[i] = 0.f;
#pragma unroll
        for (int j = 0; j < 4; j++) O[i][j] = 0.f;
    }

    int rri[4], cci[4];
#pragma unroll
    for (int i = 0; i < 4; i++) {
        int ig = q0 + ty + 16 * i;
        rri[i] = ig >> 5;
        cci[i] = ig & 31;
    }

    for (int kt = 0; kt < 16; kt++) {
        const int k0t = kt * 64;
        __syncthreads();
        for (int idx = tid; idx < 64 * 16; idx += 256) {
            int r = idx >> 4;
            int d4 = (idx & 15) * 4;
            float4 kv = *(const float4*)&Kg[(size_t)(k0t + r) * 3072 + d4];
            Ks[r * 65 + d4 + 0] = kv.x;
            Ks[r * 65 + d4 + 1] = kv.y;
            Ks[r * 65 + d4 + 2] = kv.z;
            Ks[r * 65 + d4 + 3] = kv.w;
            *(float4*)&Vs[r * 64 + d4] = *(const float4*)&Vg[(size_t)(k0t + r) * 3072 + d4];
        }
        __syncthreads();

        float s[4][4];
#pragma unroll
        for (int i = 0; i < 4; i++)
#pragma unroll
            for (int j = 0; j < 4; j++) s[i][j] = 0.f;

#pragma unroll 16
        for (int d = 0; d < 64; d++) {
            float qv[4], kv[4];
#pragma unroll
            for (int i = 0; i < 4; i++) qv[i] = Qs[(ty + 16 * i) * 64 + d];
#pragma unroll
            for (int j = 0; j < 4; j++) kv[j] = Ks[(tx + 16 * j) * 65 + d];
#pragma unroll
            for (int i = 0; i < 4; i++)
#pragma unroll
                for (int j = 0; j < 4; j++)
                    s[i][j] += qv[i] * kv[j];
        }

#pragma unroll
        for (int j = 0; j < 4; j++) {
            int jg = k0t + tx + 16 * j;
            int rj = jg >> 5, cj = jg & 31;
#pragma unroll
            for (int i = 0; i < 4; i++) {
                int dr = abs(rri[i] - rj);
                int dc = abs(cci[i] - cj);
                s[i][j] += bias_s[dr * 32 + dc];
            }
        }

#pragma unroll
        for (int i = 0; i < 4; i++) {
            float mloc = fmaxf(fmaxf(s[i][0], s[i][1]), fmaxf(s[i][2], s[i][3]));
#pragma unroll
            for (int off = 8; off >= 1; off >>= 1)
                mloc = fmaxf(mloc, __shfl_xor_sync(0xffffffffu, mloc, off));
            float mnew = fmaxf(m_i[i], mloc);
            float alpha = __expf(m_i[i] - mnew);
            m_i[i] = mnew;
            float rsum = 0.f;
#pragma unroll
            for (int j = 0; j < 4; j++) {
                s[i][j] = __expf(s[i][j] - mnew);
                rsum += s[i][j];
            }
#pragma unroll
            for (int off = 8; off >= 1; off >>= 1)
                rsum += __shfl_xor_sync(0xffffffffu, rsum, off);
            l_i[i] = l_i[i] * alpha + rsum;
#pragma unroll
            for (int j = 0; j < 4; j++) O[i][j] *= alpha;
        }

#pragma unroll
        for (int i = 0; i < 4; i++)
#pragma unroll
            for (int j = 0; j < 4; j++)
                Ps[(ty + 16 * i) * 65 + tx + 16 * j] = s[i][j];
        __syncthreads();

#pragma unroll 16
        for (int jj = 0; jj < 64; jj++) {
            float pv[4], vv[4];
#pragma unroll
            for (int i = 0; i < 4; i++) pv[i] = Ps[(ty + 16 * i) * 65 + jj];
#pragma unroll
            for (int j = 0; j < 4; j++) vv[j] = Vs[jj * 64 + tx + 16 * j];
#pragma unroll
            for (int i = 0; i < 4; i++)
#pragma unroll
                for (int j = 0; j < 4; j++)
                    O[i][j] += pv[i] * vv[j];
        }
    }

#pragma unroll
    for (int i = 0; i < 4; i++) {
        float inv = 1.f / l_i[i];
        int t = q0 + ty + 16 * i;
        float* dst = gao + ((size_t)(b * N_ + t)) * E_ + h * 64;
#pragma unroll
        for (int j = 0; j < 4; j++)
            dst[tx + 16 * j] = O[i][j] * inv;
    }
}

// ---------------------------------------------------------------------------
extern "C" void kernel_launch(void* const* d_in, const int* in_sizes, int n_in,
                              void* d_out, int out_size)
{
    (void)in_sizes; (void)n_in; (void)out_size;
    const float* x      = (const float*)d_in[0];
    const float* w_qkv  = (const float*)d_in[1];
    const float* biases = (const float*)d_in[2];
    const float* w_out  = (const float*)d_in[4];
    const float* b_out  = (const float*)d_in[5];
    float* out = (float*)d_out;

    float *qkv, *ao;
    __nv_bfloat16 *ahi, *alo, *w1hi, *w1lo, *w2hi, *w2lo, *aohi, *aolo;
    cudaGetSymbolAddress((void**)&qkv, g_qkv);
    cudaGetSymbolAddress((void**)&ao, g_ao);
    cudaGetSymbolAddress((void**)&ahi, g_ahi);
    cudaGetSymbolAddress((void**)&alo, g_alo);
    cudaGetSymbolAddress((void**)&w1hi, g_w1hi);
    cudaGetSymbolAddress((void**)&w1lo, g_w1lo);
    cudaGetSymbolAddress((void**)&w2hi, g_w2hi);
    cudaGetSymbolAddress((void**)&w2lo, g_w2lo);
    cudaGetSymbolAddress((void**)&aohi, g_aohi);
    cudaGetSymbolAddress((void**)&aolo, g_aolo);

    cudaFuncSetAttribute(gemm_hmma<0>, cudaFuncAttributeMaxDynamicSharedMemorySize, GEMM_SMEM);
    cudaFuncSetAttribute(gemm_hmma<1>, cudaFuncAttributeMaxDynamicSharedMemorySize, GEMM_SMEM);
    cudaFuncSetAttribute(attn_kernel, cudaFuncAttributeMaxDynamicSharedMemorySize, ATTN_SMEM_BYTES);

    // 1) bf16 hi/lo splits
    split_bf16<<<8192, 256>>>(x, ahi, alo, 8192 * 1024 / 4);
    split_bf16<<<3072, 256>>>(w_qkv, w1hi, w1lo, 3072 * 1024 / 4);
    split_bf16<<<1024, 256>>>(w_out, w2hi, w2lo, 1024 * 1024 / 4);

    // 2) QKV projection (HMMA): qkv[8192,3072], q pre-scaled
    {
        dim3 grid(3072 / 128, 8192 / 128);
        gemm_hmma<0><<<grid, 256, GEMM_SMEM>>>(ahi, alo, w1hi, w1lo, nullptr, qkv, 3072);
    }

    // 3) Fused attention (fp32)
    {
        dim3 grid(N_ / 64, B_ * H_);
        attn_kernel<<<grid, 256, ATTN_SMEM_BYTES>>>(qkv, biases, ao);
    }

    // 4) Split attention output, output projection (HMMA)
    split_bf16<<<8192, 256>>>(ao, aohi, aolo, 8192 * 1024 / 4);
    {
        dim3 grid(1024 / 128, 8192 / 128);
        gemm_hmma<1><<<grid, 256, GEMM_SMEM>>>(aohi, aolo, w2hi, w2lo, b_out, out, 1024);
    }
}

// round 4
// speedup vs baseline: 3.1190x; 1.8942x over previous
#include <cuda_runtime.h>
#include <cuda_bf16.h>
#include <cstdint>

#define B_ 8
#define N_ 1024
#define E_ 1024
#define H_ 16
#define D_ 64

// ---------------------------------------------------------------------------
// Static scratch (allocation-free)
// ---------------------------------------------------------------------------
#define QKV_ELEMS ((size_t)B_ * H_ * N_ * D_)
__device__ __align__(16) __nv_bfloat16 g_qh[QKV_ELEMS];
__device__ __align__(16) __nv_bfloat16 g_ql[QKV_ELEMS];
__device__ __align__(16) __nv_bfloat16 g_kh[QKV_ELEMS];
__device__ __align__(16) __nv_bfloat16 g_kl[QKV_ELEMS];
__device__ __align__(16) __nv_bfloat16 g_vh[QKV_ELEMS];
__device__ __align__(16) __nv_bfloat16 g_vl[QKV_ELEMS];
__device__ __align__(16) __nv_bfloat16 g_ahi[(size_t)8192 * 1024];
__device__ __align__(16) __nv_bfloat16 g_alo[(size_t)8192 * 1024];
__device__ __align__(16) __nv_bfloat16 g_w1hi[(size_t)3072 * 1024];
__device__ __align__(16) __nv_bfloat16 g_w1lo[(size_t)3072 * 1024];
__device__ __align__(16) __nv_bfloat16 g_w2hi[(size_t)1024 * 1024];
__device__ __align__(16) __nv_bfloat16 g_w2lo[(size_t)1024 * 1024];
__device__ __align__(16) __nv_bfloat16 g_aohi[(size_t)8192 * 1024];
__device__ __align__(16) __nv_bfloat16 g_aolo[(size_t)8192 * 1024];

__device__ __forceinline__ uint32_t smem_to_u32(const void* p) {
    uint32_t a;
    asm("{ .reg .u64 t; cvta.to.shared.u64 t, %1; cvt.u32.u64 %0, t; }" : "=r"(a) : "l"(p));
    return a;
}
#define SWZ(o) ((o) ^ (((o) >> 3) & 0x70))

__device__ __forceinline__ void ldsm_x4(uint32_t* d, uint32_t addr) {
    asm volatile("ldmatrix.sync.aligned.m8n8.x4.shared.b16 {%0,%1,%2,%3}, [%4];"
                 : "=r"(d[0]), "=r"(d[1]), "=r"(d[2]), "=r"(d[3]) : "r"(addr));
}
__device__ __forceinline__ void ldsm_x4_t(uint32_t* d, uint32_t addr) {
    asm volatile("ldmatrix.sync.aligned.m8n8.x4.trans.shared.b16 {%0,%1,%2,%3}, [%4];"
                 : "=r"(d[0]), "=r"(d[1]), "=r"(d[2]), "=r"(d[3]) : "r"(addr));
}
__device__ __forceinline__ void mma_bf16(float* c, const uint32_t* a, uint32_t b0, uint32_t b1) {
    asm volatile(
        "mma.sync.aligned.m16n8k16.row.col.f32.bf16.bf16.f32 "
        "{%0,%1,%2,%3}, {%4,%5,%6,%7}, {%8,%9}, {%0,%1,%2,%3};"
        : "+f"(c[0]), "+f"(c[1]), "+f"(c[2]), "+f"(c[3])
        : "r"(a[0]), "r"(a[1]), "r"(a[2]), "r"(a[3]), "r"(b0), "r"(b1));
}
__device__ __forceinline__ void cp_async16(uint32_t sdst, const void* gsrc) {
    asm volatile("cp.async.cg.shared.global [%0], [%1], 16;" :: "r"(sdst), "l"(gsrc));
}
#define CP_COMMIT() asm volatile("cp.async.commit_group;" ::: "memory")
#define CP_WAIT_ALL() asm volatile("cp.async.wait_group 0;" ::: "memory")

// pack two floats into bf16x2 hi/lo error-split pairs (low half = first arg)
__device__ __forceinline__ void split2(float a, float b, uint32_t& hi2, uint32_t& lo2) {
    __nv_bfloat16 ah = __float2bfloat16_rn(a);
    __nv_bfloat16 bh = __float2bfloat16_rn(b);
    __nv_bfloat16 al = __float2bfloat16_rn(a - __bfloat162float(ah));
    __nv_bfloat16 bl = __float2bfloat16_rn(b - __bfloat162float(bh));
    __nv_bfloat162 h2; h2.x = ah; h2.y = bh;
    __nv_bfloat162 l2; l2.x = al; l2.y = bl;
    hi2 = *reinterpret_cast<uint32_t*>(&h2);
    lo2 = *reinterpret_cast<uint32_t*>(&l2);
}

// ---------------------------------------------------------------------------
// fp32 -> (bf16 hi, bf16 lo) split
// ---------------------------------------------------------------------------
__global__ __launch_bounds__(256) void split_bf16(
    const float* __restrict__ x, __nv_bfloat16* __restrict__ hi,
    __nv_bfloat16* __restrict__ lo, int n4)
{
    int i = blockIdx.x * 256 + threadIdx.x;
    if (i >= n4) return;
    float4 v = ((const float4*)x)[i];
    float vv[4] = {v.x, v.y, v.z, v.w};
    ushort4 h, l;
    unsigned short* hp = &h.x;
    unsigned short* lp = &l.x;
#pragma unroll
    for (int j = 0; j < 4; j++) {
        __nv_bfloat16 bh = __float2bfloat16_rn(vv[j]);
        __nv_bfloat16 bl = __float2bfloat16_rn(vv[j] - __bfloat162float(bh));
        hp[j] = *reinterpret_cast<unsigned short*>(&bh);
        lp[j] = *reinterpret_cast<unsigned short*>(&bl);
    }
    ((ushort4*)hi)[i] = h;
    ((ushort4*)lo)[i] = l;
}

// ---------------------------------------------------------------------------
// HMMA bf16-split GEMM (NT), K=1024, 128x128 tile, 8 warps, BK=64, cp.async x2.
// MODE 0: scatter q/k/v bf16 hi/lo head-major; q scaled 0.125
// MODE 1: C = acc + bias[n] -> fp32 out
// ---------------------------------------------------------------------------
#define STAGE_BYTES 65536
#define GEMM_SMEM (2 * STAGE_BYTES)

template <int MODE>
__global__ __launch_bounds__(256, 1)
void gemm_hmma(const __nv_bfloat16* __restrict__ Ah, const __nv_bfloat16* __restrict__ Al,
               const __nv_bfloat16* __restrict__ Bh, const __nv_bfloat16* __restrict__ Bl,
               const float* __restrict__ bias, float* __restrict__ C, int ldc,
               __nv_bfloat16* __restrict__ OQH, __nv_bfloat16* __restrict__ OQL,
               __nv_bfloat16* __restrict__ OKH, __nv_bfloat16* __restrict__ OKL,
               __nv_bfloat16* __restrict__ OVH, __nv_bfloat16* __restrict__ OVL)
{
    extern __shared__ char smem[];
    const uint32_t sb = smem_to_u32(smem);
    const int tid = threadIdx.x;
    const int wid = tid >> 5, lane = tid & 31;
    const int bm = blockIdx.y * 128, bn = blockIdx.x * 128;
    const int wm = wid >> 1, wn = wid & 1;

    const __nv_bfloat16* tb[4] = {
        Ah + (size_t)bm * 1024, Al + (size_t)bm * 1024,
        Bh + (size_t)bn * 1024, Bl + (size_t)bn * 1024 };

    const int rb = tid >> 3;
    const int cg = tid & 7;
    uint32_t soff[4];
#pragma unroll
    for (int it = 0; it < 4; it++)
        soff[it] = SWZ((uint32_t)((rb + it * 32) * 128 + cg * 16));

    const int q = lane >> 3, l8 = lane & 7;
    const int ar = wm * 32 + (q & 1) * 8 + l8;
    const int ac = (q >> 1) * 16;
    const int br = wn * 64 + (q >> 1) * 8 + l8;
    const int bc = (q & 1) * 16;

    float acc[2][8][4];
#pragma unroll
    for (int mt = 0; mt < 2; mt++)
#pragma unroll
        for (int nt = 0; nt < 8; nt++)
#pragma unroll
            for (int e = 0; e < 4; e++) acc[mt][nt][e] = 0.f;

#define ISSUE(kc_, buf_) do {                                                   \
    const uint32_t stage = sb + (uint32_t)(buf_) * STAGE_BYTES;                 \
    _Pragma("unroll")                                                           \
    for (int t = 0; t < 4; t++) {                                               \
        const __nv_bfloat16* gp = tb[t] + (size_t)(kc_) * 64 + cg * 8;          \
        const uint32_t tbase = stage + (uint32_t)t * 16384u;                    \
        _Pragma("unroll")                                                       \
        for (int it = 0; it < 4; it++)                                          \
            cp_async16(tbase + soff[it], gp + (size_t)(rb + it * 32) * 1024);   \
    }                                                                           \
    CP_COMMIT();                                                                \
} while (0)

    ISSUE(0, 0);

    for (int kc = 0; kc < 16; kc++) {
        const int buf = kc & 1;
        CP_WAIT_ALL();
        __syncthreads();
        if (kc < 15) ISSUE(kc + 1, buf ^ 1);

        const uint32_t stage = sb + (uint32_t)buf * STAGE_BYTES;
        const uint32_t sAh = stage, sAl = stage + 16384u;
        const uint32_t sBh = stage + 32768u, sBl = stage + 49152u;

#pragma unroll
        for (int ks = 0; ks < 4; ks++) {
            uint32_t ah[2][4], al[2][4];
#pragma unroll
            for (int mt = 0; mt < 2; mt++) {
                const uint32_t off = SWZ((uint32_t)((ar + mt * 16) * 128 + ac + ks * 32));
                ldsm_x4(ah[mt], sAh + off);
                ldsm_x4(al[mt], sAl + off);
            }
            uint32_t bh[4][4], bl[4][4];
#pragma unroll
            for (int jp = 0; jp < 4; jp++) {
                const uint32_t off = SWZ((uint32_t)((br + jp * 16) * 128 + bc + ks * 32));
                ldsm_x4(bh[jp], sBh + off);
                ldsm_x4(bl[jp], sBl + off);
            }
#pragma unroll
            for (int mt = 0; mt < 2; mt++)
#pragma unroll
                for (int jp = 0; jp < 4; jp++) {
                    mma_bf16(acc[mt][2 * jp + 0], ah[mt], bh[jp][0], bh[jp][1]);
                    mma_bf16(acc[mt][2 * jp + 1], ah[mt], bh[jp][2], bh[jp][3]);
                    mma_bf16(acc[mt][2 * jp + 0], ah[mt], bl[jp][0], bl[jp][1]);
                    mma_bf16(acc[mt][2 * jp + 1], ah[mt], bl[jp][2], bl[jp][3]);
                    mma_bf16(acc[mt][2 * jp + 0], al[mt], bh[jp][0], bh[jp][1]);
                    mma_bf16(acc[mt][2 * jp + 1], al[mt], bh[jp][2], bh[jp][3]);
                }
        }
        __syncthreads();
    }
#undef ISSUE

    const int g = lane >> 2, tg = lane & 3;
    if (MODE == 0) {
        const int which = bn >> 10;
        __nv_bfloat16* dh = (which == 0) ? OQH : ((which == 1) ? OKH : OVH);
        __nv_bfloat16* dl = (which == 0) ? OQL : ((which == 1) ? OKL : OVL);
        const float sc = (which == 0) ? 0.125f : 1.0f;
#pragma unroll
        for (int mt = 0; mt < 2; mt++) {
            const int row0 = bm + wm * 32 + mt * 16 + g;
            const int bidx = row0 >> 10, tt = row0 & 1023;
#pragma unroll
            for (int nt = 0; nt < 8; nt++) {
                const int col = bn + wn * 64 + nt * 8 + tg * 2;
                const int e = col & 1023, hh = e >> 6, dd = e & 63;
                const size_t i0 = (((size_t)bidx * 16 + hh) * 1024 + tt) * 64 + dd;
                uint32_t h2, l2;
                split2(acc[mt][nt][0] * sc, acc[mt][nt][1] * sc, h2, l2);
                *(uint32_t*)(dh + i0) = h2;
                *(uint32_t*)(dl + i0) = l2;
                split2(acc[mt][nt][2] * sc, acc[mt][nt][3] * sc, h2, l2);
                *(uint32_t*)(dh + i0 + 8 * 64) = h2;
                *(uint32_t*)(dl + i0 + 8 * 64) = l2;
            }
        }
    } else {
#pragma unroll
        for (int mt = 0; mt < 2; mt++) {
            const int row0 = bm + wm * 32 + mt * 16 + g;
#pragma unroll
            for (int nt = 0; nt < 8; nt++) {
                const int col = bn + wn * 64 + nt * 8 + tg * 2;
                const float b0v = bias[col], b1v = bias[col + 1];
                *(float2*)(C + (size_t)row0 * ldc + col) =
                    make_float2(acc[mt][nt][0] + b0v, acc[mt][nt][1] + b1v);
                *(float2*)(C + (size_t)(row0 + 8) * ldc + col) =
                    make_float2(acc[mt][nt][2] + b0v, acc[mt][nt][3] + b1v);
            }
        }
    }
}

// ---------------------------------------------------------------------------
// Tensor-core flash attention, bf16 3-term splits for QK^T and PV.
// One CTA per (bh, 128-query tile). 8 warps, each owns 16 query rows.
// smem: bias 4KB | Qh/Ql 32KB | KV double buffer 2x32KB = 102400 B.
// ---------------------------------------------------------------------------
#define AT_QOFF 4096u
#define AT_KVOFF 36864u
#define AT_SMEM (4096 + 32768 + 65536)

__global__ __launch_bounds__(256, 1) void attn_tc(
    const __nv_bfloat16* __restrict__ qh_, const __nv_bfloat16* __restrict__ ql_,
    const __nv_bfloat16* __restrict__ kh_, const __nv_bfloat16* __restrict__ kl_,
    const __nv_bfloat16* __restrict__ vh_, const __nv_bfloat16* __restrict__ vl_,
    const float* __restrict__ biases,
    __nv_bfloat16* __restrict__ aohi, __nv_bfloat16* __restrict__ aolo)
{
    extern __shared__ char smem[];
    const uint32_t sb = smem_to_u32(smem);
    const int tid = threadIdx.x, wid = tid >> 5, lane = tid & 31;
    const int g = lane >> 2, tg = lane & 3, qq = lane >> 3, l8 = lane & 7;
    const int qi = blockIdx.x, bh = blockIdx.y;
    const int b = bh >> 4, h = bh & 15;
    const int m0 = wid * 16;
    const size_t hb = (size_t)bh << 16;   // bh * 1024 * 64

    float* bias_s = (float*)smem;
    for (int i = tid; i < 1024; i += 256) bias_s[i] = biases[h * 1024 + i];

    // stage Q (hi/lo), 128 rows x 64 bf16, SW128
    {
        const __nv_bfloat16* srcs[2] = { qh_ + hb + (size_t)(qi * 128) * 64,
                                         ql_ + hb + (size_t)(qi * 128) * 64 };
#pragma unroll
        for (int t = 0; t < 2; t++)
#pragma unroll
            for (int i2 = 0; i2 < 4; i2++) {
                const int idx = tid + 256 * i2;
                const int r = idx >> 3, c = idx & 7;
                cp_async16(sb + AT_QOFF + t * 16384u + SWZ((uint32_t)(r * 128 + c * 16)),
                           srcs[t] + (size_t)r * 64 + c * 8);
            }
        CP_COMMIT();
    }

    const __nv_bfloat16* kvp[4] = { kh_ + hb, kl_ + hb, vh_ + hb, vl_ + hb };

#define ISSUE_KV(kt_, buf_) do {                                                  \
    const uint32_t st = sb + AT_KVOFF + (uint32_t)(buf_) * 32768u;                \
    _Pragma("unroll")                                                             \
    for (int t = 0; t < 4; t++) {                                                 \
        const __nv_bfloat16* gp = kvp[t] + (size_t)((kt_) * 64) * 64;             \
        _Pragma("unroll")                                                         \
        for (int i2 = 0; i2 < 2; i2++) {                                          \
            const int idx = tid + 256 * i2;                                       \
            const int r = idx >> 3, c = idx & 7;                                  \
            cp_async16(st + t * 8192u + SWZ((uint32_t)(r * 128 + c * 16)),        \
                       gp + (size_t)r * 64 + c * 8);                              \
        }                                                                         \
    }                                                                             \
    CP_COMMIT();                                                                  \
} while (0)

    ISSUE_KV(0, 0);
    CP_WAIT_ALL();
    __syncthreads();

    // Q fragments resident in registers (4 k-steps, hi/lo)
    uint32_t qfh[4][4], qfl[4][4];
#pragma unroll
    for (int ks = 0; ks < 4; ks++) {
        const uint32_t off =
            SWZ((uint32_t)((m0 + (qq & 1) * 8 + l8) * 128 + (qq >> 1) * 16 + ks * 32));
        ldsm_x4(qfh[ks], sb + AT_QOFF + off);
        ldsm_x4(qfl[ks], sb + AT_QOFF + 16384u + off);
    }

    float O[8][4];
#pragma unroll
    for (int dt = 0; dt < 8; dt++)
#pragma unroll
        for (int e = 0; e < 4; e++) O[dt][e] = 0.f;
    float mr0 = -1e30f, mr1 = -1e30f, lr0 = 0.f, lr1 = 0.f;

    const int i0 = qi * 128 + m0 + g;
    const int ir0 = i0 >> 5, ic0 = i0 & 31;
    const int ir1 = (i0 + 8) >> 5, ic1 = (i0 + 8) & 31;

    for (int kt = 0; kt < 16; kt++) {
        if (kt > 0) { CP_WAIT_ALL(); __syncthreads(); }
        if (kt < 15) ISSUE_KV(kt + 1, (kt + 1) & 1);
        const uint32_t kb = sb + AT_KVOFF + (uint32_t)(kt & 1) * 32768u;

        // ---- S = Q K^T (3-term) ----
        float s[8][4];
#pragma unroll
        for (int t = 0; t < 8; t++)
#pragma unroll
            for (int e = 0; e < 4; e++) s[t][e] = 0.f;

#pragma unroll
        for (int ks = 0; ks < 4; ks++) {
#pragma unroll
            for (int jp = 0; jp < 4; jp++) {
                uint32_t khf[4], klf[4];
                const uint32_t off = SWZ((uint32_t)(
                    ((qq >> 1) * 8 + l8 + jp * 16) * 128 + (qq & 1) * 16 + ks * 32));
                ldsm_x4(khf, kb + off);
                ldsm_x4(klf, kb + 8192u + off);
                mma_bf16(s[2 * jp + 0], qfh[ks], khf[0], khf[1]);
                mma_bf16(s[2 * jp + 1], qfh[ks], khf[2], khf[3]);
                mma_bf16(s[2 * jp + 0], qfh[ks], klf[0], klf[1]);
                mma_bf16(s[2 * jp + 1], qfh[ks], klf[2], klf[3]);
                mma_bf16(s[2 * jp + 0], qfl[ks], khf[0], khf[1]);
                mma_bf16(s[2 * jp + 1], qfl[ks], khf[2], khf[3]);
            }
        }

        // ---- relative-position bias ----
#pragma unroll
        for (int t = 0; t < 8; t++) {
            const int j0 = kt * 64 + t * 8 + tg * 2;
            const int jr0 = j0 >> 5, jc0 = j0 & 31;
            const int jr1 = (j0 + 1) >> 5, jc1 = (j0 + 1) & 31;
            s[t][0] += bias_s[abs(ir0 - jr0) * 32 + abs(ic0 - jc0)];
            s[t][1] += bias_s[abs(ir0 - jr1) * 32 + abs(ic0 - jc1)];
            s[t][2] += bias_s[abs(ir1 - jr0) * 32 + abs(ic1 - jc0)];
            s[t][3] += bias_s[abs(ir1 - jr1) * 32 + abs(ic1 - jc1)];
        }

        // ---- online softmax (rows g, g+8; stats across 4 lanes of the quad) ----
        float mx0 = -1e30f, mx1 = -1e30f;
#pragma unroll
        for (int t = 0; t < 8; t++) {
            mx0 = fmaxf(mx0, fmaxf(s[t][0], s[t][1]));
            mx1 = fmaxf(mx1, fmaxf(s[t][2], s[t][3]));
        }
        mx0 = fmaxf(mx0, __shfl_xor_sync(0xffffffffu, mx0, 1));
        mx0 = fmaxf(mx0, __shfl_xor_sync(0xffffffffu, mx0, 2));
        mx1 = fmaxf(mx1, __shfl_xor_sync(0xffffffffu, mx1, 1));
        mx1 = fmaxf(mx1, __shfl_xor_sync(0xffffffffu, mx1, 2));
        const float mn0 = fmaxf(mr0, mx0), mn1 = fmaxf(mr1, mx1);
        const float a0 = __expf(mr0 - mn0), a1 = __expf(mr1 - mn1);
        mr0 = mn0; mr1 = mn1;
        float sum0 = 0.f, sum1 = 0.f;
#pragma unroll
        for (int t = 0; t < 8; t++) {
            s[t][0] = __expf(s[t][0] - mn0); sum0 += s[t][0];
            s[t][1] = __expf(s[t][1] - mn0); sum0 += s[t][1];
            s[t][2] = __expf(s[t][2] - mn1); sum1 += s[t][2];
            s[t][3] = __expf(s[t][3] - mn1); sum1 += s[t][3];
        }
        sum0 += __shfl_xor_sync(0xffffffffu, sum0, 1);
        sum0 += __shfl_xor_sync(0xffffffffu, sum0, 2);
        sum1 += __shfl_xor_sync(0xffffffffu, sum1, 1);
        sum1 += __shfl_xor_sync(0xffffffffu, sum1, 2);
        lr0 = lr0 * a0 + sum0;
        lr1 = lr1 * a1 + sum1;
#pragma unroll
        for (int dt = 0; dt < 8; dt++) {
            O[dt][0] *= a0; O[dt][1] *= a0;
            O[dt][2] *= a1; O[dt][3] *= a1;
        }

        // ---- O += P V (3-term), P converted in-register to A fragments ----
#pragma unroll
        for (int js = 0; js < 4; js++) {
            uint32_t aph[4], apl[4];
            split2(s[2 * js][0],     s[2 * js][1],     aph[0], apl[0]);
            split2(s[2 * js][2],     s[2 * js][3],     aph[1], apl[1]);
            split2(s[2 * js + 1][0], s[2 * js + 1][1], aph[2], apl[2]);
            split2(s[2 * js + 1][2], s[2 * js + 1][3], aph[3], apl[3]);
#pragma unroll
            for (int dp = 0; dp < 4; dp++) {
                uint32_t vhf[4], vlf[4];
                const uint32_t off = SWZ((uint32_t)(
                    (js * 16 + (qq & 1) * 8 + l8) * 128 + dp * 32 + (qq >> 1) * 16));
                ldsm_x4_t(vhf, kb + 16384u + off);
                ldsm_x4_t(vlf, kb + 24576u + off);
                mma_bf16(O[2 * dp + 0], aph, vhf[0], vhf[1]);
                mma_bf16(O[2 * dp + 1], aph, vhf[2], vhf[3]);
                mma_bf16(O[2 * dp + 0], aph, vlf[0], vlf[1]);
                mma_bf16(O[2 * dp + 1], aph, vlf[2], vlf[3]);
                mma_bf16(O[2 * dp + 0], apl, vhf[0], vhf[1]);
                mma_bf16(O[2 * dp + 1], apl, vhf[2], vhf[3]);
            }
        }
    }
#undef ISSUE_KV

    // ---- epilogue: normalize, split to bf16 hi/lo, token-major out ----
    const float inv0 = 1.f / lr0, inv1 = 1.f / lr1;
    const int t0 = qi * 128 + m0 + g;
    const size_t base0 = ((size_t)(b * 1024 + t0)) * 1024 + h * 64;
    const size_t base1 = base0 + 8 * 1024;
#pragma unroll
    for (int dt = 0; dt < 8; dt++) {
        const int d0 = dt * 8 + tg * 2;
        uint32_t h2, l2;
        split2(O[dt][0] * inv0, O[dt][1] * inv0, h2, l2);
        *(uint32_t*)(aohi + base0 + d0) = h2;
        *(uint32_t*)(aolo + base0 + d0) = l2;
        split2(O[dt][2] * inv1, O[dt][3] * inv1, h2, l2);
        *(uint32_t*)(aohi + base1 + d0) = h2;
        *(uint32_t*)(aolo + base1 + d0) = l2;
    }
}

// ---------------------------------------------------------------------------
extern "C" void kernel_launch(void* const* d_in, const int* in_sizes, int n_in,
                              void* d_out, int out_size)
{
    (void)in_sizes; (void)n_in; (void)out_size;
    const float* x      = (const float*)d_in[0];
    const float* w_qkv  = (const float*)d_in[1];
    const float* biases = (const float*)d_in[2];
    const float* w_out  = (const float*)d_in[4];
    const float* b_out  = (const float*)d_in[5];
    float* out = (float*)d_out;

    __nv_bfloat16 *qh, *ql, *kh, *kl, *vh, *vl;
    __nv_bfloat16 *ahi, *alo, *w1hi, *w1lo, *w2hi, *w2lo, *aohi, *aolo;
    cudaGetSymbolAddress((void**)&qh, g_qh);
    cudaGetSymbolAddress((void**)&ql, g_ql);
    cudaGetSymbolAddress((void**)&kh, g_kh);
    cudaGetSymbolAddress((void**)&kl, g_kl);
    cudaGetSymbolAddress((void**)&vh, g_vh);
    cudaGetSymbolAddress((void**)&vl, g_vl);
    cudaGetSymbolAddress((void**)&ahi, g_ahi);
    cudaGetSymbolAddress((void**)&alo, g_alo);
    cudaGetSymbolAddress((void**)&w1hi, g_w1hi);
    cudaGetSymbolAddress((void**)&w1lo, g_w1lo);
    cudaGetSymbolAddress((void**)&w2hi, g_w2hi);
    cudaGetSymbolAddress((void**)&w2lo, g_w2lo);
    cudaGetSymbolAddress((void**)&aohi, g_aohi);
    cudaGetSymbolAddress((void**)&aolo, g_aolo);

    cudaFuncSetAttribute(gemm_hmma<0>, cudaFuncAttributeMaxDynamicSharedMemorySize, GEMM_SMEM);
    cudaFuncSetAttribute(gemm_hmma<1>, cudaFuncAttributeMaxDynamicSharedMemorySize, GEMM_SMEM);
    cudaFuncSetAttribute(attn_tc, cudaFuncAttributeMaxDynamicSharedMemorySize, AT_SMEM);

    // 1) bf16 hi/lo splits of inputs
    split_bf16<<<8192, 256>>>(x, ahi, alo, 8192 * 1024 / 4);
    split_bf16<<<3072, 256>>>(w_qkv, w1hi, w1lo, 3072 * 1024 / 4);
    split_bf16<<<1024, 256>>>(w_out, w2hi, w2lo, 1024 * 1024 / 4);

    // 2) QKV projection -> head-major bf16 hi/lo q/k/v (q pre-scaled)
    {
        dim3 grid(3072 / 128, 8192 / 128);
        gemm_hmma<0><<<grid, 256, GEMM_SMEM>>>(ahi, alo, w1hi, w1lo, nullptr, nullptr, 0,
                                               qh, ql, kh, kl, vh, vl);
    }

    // 3) Tensor-core flash attention -> aohi/aolo
    {
        dim3 grid(8, 128);
        attn_tc<<<grid, 256, AT_SMEM>>>(qh, ql, kh, kl, vh, vl, biases, aohi, aolo);
    }

    // 4) Output projection + bias -> fp32 out
    {
        dim3 grid(1024 / 128, 8192 / 128);
        gemm_hmma<1><<<grid, 256, GEMM_SMEM>>>(aohi, aolo, w2hi, w2lo, b_out, out, 1024,
                                               nullptr, nullptr, nullptr, nullptr, nullptr, nullptr);
    }
}